// round 9
// baseline (speedup 1.0000x reference)
#include <cuda_runtime.h>
#include <cstdint>

// Problem constants
#define PB 8
#define PS 2048
#define PH 2048
#define NTOK (PB*PS)         // 16384

// Output layout: concatenated returns (all float32)
#define O_MH  0L
#define O_MAM (O_MH  + (long)PB*PS*PH)   // 33554432
#define O_MS  (O_MAM + (long)PB*PS)
#define O_CNT (O_MS  + (long)PB*PS)
#define O_MM  (O_CNT + (long)PB*PS)
#define O_LOG (O_MM  + (long)PB*PS*2)

// Scratch (device globals; no allocation allowed)
__device__ float4 g_dots[NTOK];      // per token: (h·Wa0, h·Wa1, h·Wb0, h·Wb1)
__device__ float  g_v[NTOK];
__device__ int    g_segstart[NTOK];
__device__ int    g_newlen[PB];
__device__ int    g_T[PB];

// ---------------------------------------------------------------------------
// Kernel A: per-token 4-way dot products. 16 tokens per block (2 per warp),
// W staged in shared (32KB). grid=1024 so ~6 blocks/SM actually fill the chip
// (R3's grid=512 capped occupancy at 43%).
// ---------------------------------------------------------------------------
__global__ __launch_bounds__(256, 6) void k_dots(const float* __restrict__ h,
                                                 const float* __restrict__ W) {
    __shared__ float4 sW[PH];   // sW[k] = (Wa[k,0], Wa[k,1], Wb[k,0], Wb[k,1])
    const int tid = threadIdx.x;
    const float2* W2 = (const float2*)W;   // W is [4096,2] row-major
    for (int k = tid; k < PH; k += 256) {
        float2 wa = W2[k];
        float2 wb = W2[PH + k];
        sW[k] = make_float4(wa.x, wa.y, wb.x, wb.y);
    }
    __syncthreads();

    const int warp = tid >> 5, lane = tid & 31;
    const long g0 = (long)blockIdx.x * 16 + warp * 2;  // 2 tokens per warp
    const float4* hp = ((const float4*)h) + g0 * (PH/4);

    float a[2][4];
    #pragma unroll
    for (int i = 0; i < 2; i++)
        #pragma unroll
        for (int c = 0; c < 4; c++) a[i][c] = 0.f;

    #pragma unroll 4
    for (int j = 0; j < 16; j++) {
        const int f = lane + 32 * j;           // float4 index within row
        float4 x[2];
        #pragma unroll
        for (int i = 0; i < 2; i++) x[i] = hp[(long)i * (PH/4) + f];
        #pragma unroll
        for (int k = 0; k < 4; k++) {
            const float4 w = sW[4*f + k];
            #pragma unroll
            for (int i = 0; i < 2; i++) {
                const float xs = (k == 0) ? x[i].x : (k == 1) ? x[i].y
                               : (k == 2) ? x[i].z : x[i].w;
                a[i][0] += xs * w.x;
                a[i][1] += xs * w.y;
                a[i][2] += xs * w.z;
                a[i][3] += xs * w.w;
            }
        }
    }
    #pragma unroll
    for (int i = 0; i < 2; i++) {
        float v0 = a[i][0], v1 = a[i][1], v2 = a[i][2], v3 = a[i][3];
        #pragma unroll
        for (int o = 16; o > 0; o >>= 1) {
            v0 += __shfl_down_sync(0xFFFFFFFFu, v0, o);
            v1 += __shfl_down_sync(0xFFFFFFFFu, v1, o);
            v2 += __shfl_down_sync(0xFFFFFFFFu, v2, o);
            v3 += __shfl_down_sync(0xFFFFFFFFu, v3, o);
        }
        if (lane == 0) g_dots[g0 + i] = make_float4(v0, v1, v2, v3);
    }
}

// ---------------------------------------------------------------------------
// Kernel B: logits, gumbel argmax -> mm, per-batch run-length scan.
// One block per batch, 1024 threads, 2 positions per thread.
// ---------------------------------------------------------------------------
__global__ __launch_bounds__(1024) void k_scan(const float* __restrict__ gum,
                                               const int*   __restrict__ mask,
                                               const int*   __restrict__ special,
                                               const float* __restrict__ bias,
                                               float* __restrict__ out) {
    const int b = blockIdx.x, tid = threadIdx.x;
    __shared__ unsigned char sh_want[PS];
    __shared__ int sh_r[PS];
    __shared__ int sh_seg[PS];
    __shared__ int sh_scan[1024];
    __shared__ int warpsum[32];
    __shared__ int sh_T;

    const long base = (long)b * PS;

    const int m0 = mask[base + 2*tid], m1 = mask[base + 2*tid + 1];
    int partial = m0 + m1;
    #pragma unroll
    for (int o = 16; o > 0; o >>= 1) partial += __shfl_down_sync(0xFFFFFFFFu, partial, o);
    if ((tid & 31) == 0) warpsum[tid >> 5] = partial;
    __syncthreads();
    if (tid == 0) {
        int t = 0;
        #pragma unroll
        for (int i = 0; i < 32; i++) t += warpsum[i];
        sh_T = t;
    }
    __syncthreads();
    const int T = sh_T;
    const float b0 = bias[0], b1 = bias[1];

    float mmv[2][2], lg[2][2];
    #pragma unroll
    for (int p = 0; p < 2; p++) {
        const int s = 2*tid + p;
        const long gi = base + s;
        float l0, l1;
        if (s < PS - 1) {
            const float4 d0 = g_dots[gi];
            const float4 d1 = g_dots[gi + 1];
            l0 = d0.x + d1.z + b0;
            l1 = d0.y + d1.w + b1;
        } else { l0 = b0; l1 = b1; }
        lg[p][0] = l0; lg[p][1] = l1;
        const float gg0 = gum[gi*2], gg1 = gum[gi*2 + 1];
        const int idx1 = (l1 + gg1) > (l0 + gg0);  // argmax: first index wins ties
        float mm0 = idx1 ? 0.f : 1.f;
        float mm1 = idx1 ? 1.f : 0.f;
        if (special[gi]) { mm0 = 1.f; mm1 = 0.f; }
        const float mk = (float)((p == 0) ? m0 : m1);
        mm0 *= mk; mm1 *= mk;
        mmv[p][0] = mm0; mmv[p][1] = mm1;
        sh_want[s] = (mm1 > 0.5f) && (s >= 1) && (s < T - 1);
    }
    __syncthreads();

    int inc0, inc1;
    {
        const int s0 = 2*tid;
        inc0 = (s0 >= 1 && s0 < T) && !(sh_want[s0] && sh_want[s0-1]);
        const int s1 = 2*tid + 1;
        inc1 = (s1 < T) && !(sh_want[s1] && sh_want[s1-1]);
    }
    const int local = inc0 + inc1;
    sh_scan[tid] = local;
    __syncthreads();
    for (int off = 1; off < 1024; off <<= 1) {
        const int val = sh_scan[tid];
        const int add = (tid >= off) ? sh_scan[tid - off] : 0;
        __syncthreads();
        sh_scan[tid] = val + add;
        __syncthreads();
    }
    const int excl = sh_scan[tid] - local;
    const int r0 = excl + inc0;
    const int r1 = r0 + inc1;
    sh_r[2*tid]     = r0;
    sh_r[2*tid + 1] = r1;
    __syncthreads();
    const int new_len = sh_r[PS - 1] + 1;

    #pragma unroll
    for (int p = 0; p < 2; p++) {
        const int s = 2*tid + p;
        const int rr = sh_r[s];
        if (s == 0 || sh_r[s-1] != rr) sh_seg[rr] = s;
    }
    __syncthreads();

    #pragma unroll
    for (int p = 0; p < 2; p++) {
        const int s = 2*tid + p;
        const long gi = base + s;
        const bool want = sh_want[s];
        float v = want ? mmv[p][1] : mmv[p][0];
        if (s == 0) v = 1.f;
        if (s >= T) v = 0.f;
        g_v[gi] = v;

        ((float2*)(out + O_MM ))[gi] = make_float2(mmv[p][0], mmv[p][1]);
        ((float2*)(out + O_LOG))[gi] = make_float2(lg[p][0], lg[p][1]);

        const int t = s;  // output-row index
        float cnt = 0.f, mam = 0.f, msp = 0.f;
        if (t < new_len) {
            const int e = (t + 1 < new_len) ? sh_seg[t + 1] : T;
            cnt = (float)(e - sh_seg[t]);
            mam = 1.f;
            msp = (t == 0 || t == new_len - 1) ? 1.f : 0.f;
            g_segstart[gi] = sh_seg[t];
        }
        out[O_CNT + gi] = cnt;
        out[O_MAM + gi] = mam;
        out[O_MS  + gi] = msp;
    }
    if (tid == 0) { g_newlen[b] = new_len; g_T[b] = T; }
}

// ---------------------------------------------------------------------------
// Kernel C: merged_hidden via segment sums. One block per output row.
// Reversed block->token order to consume k_dots' L2-resident tail of h first.
// h reads are single-use here (transform rows partition inputs) -> __ldcs.
// Output stores __stcs so 134MB of writes don't evict other blocks' h lines.
// Branch-free inner loop so loads batch (MLP).
// ---------------------------------------------------------------------------
__global__ __launch_bounds__(256) void k_merge(const float* __restrict__ h,
                                               float* __restrict__ out) {
    const int idx = NTOK - 1 - blockIdx.x;   // reversed
    const int t = idx & (PS - 1);
    const int b = idx >> 11;
    const int tid = threadIdx.x;
    const int nl = g_newlen[b];
    float4* op = ((float4*)(out + O_MH)) + ((long)idx) * (PH/4);

    if (t >= nl) {
        const float4 z = make_float4(0.f, 0.f, 0.f, 0.f);
        __stcs(op + tid, z);
        __stcs(op + tid + 256, z);
        return;
    }
    const long base = (long)b * PS;
    const int s0 = g_segstart[base + t];
    const int s1 = (t + 1 < nl) ? g_segstart[base + t + 1] : g_T[b];
    float4 a0 = make_float4(0.f,0.f,0.f,0.f);
    float4 a1 = make_float4(0.f,0.f,0.f,0.f);
    #pragma unroll 2
    for (int s = s1 - 1; s >= s0; s--) {        // high addresses first (hotter in L2)
        const float vv = g_v[base + s];
        const float4* hp = ((const float4*)h) + (base + s) * (long)(PH/4);
        const float4 x0 = __ldcs(hp + tid);
        const float4 x1 = __ldcs(hp + tid + 256);
        a0.x += vv*x0.x; a0.y += vv*x0.y; a0.z += vv*x0.z; a0.w += vv*x0.w;
        a1.x += vv*x1.x; a1.y += vv*x1.y; a1.z += vv*x1.z; a1.w += vv*x1.w;
    }
    __stcs(op + tid, a0);
    __stcs(op + tid + 256, a1);
}

// ---------------------------------------------------------------------------
extern "C" void kernel_launch(void* const* d_in, const int* in_sizes, int n_in,
                              void* d_out, int out_size) {
    const float* h       = (const float*)d_in[0];  // [8,2048,2048] f32
    const int*   mask    = (const int*)  d_in[1];  // [8,2048] i32
    const int*   special = (const int*)  d_in[2];  // [8,2048] i32
    const float* gum     = (const float*)d_in[3];  // [8,2048,2] f32
    const float* W       = (const float*)d_in[4];  // [4096,2] f32
    const float* bias    = (const float*)d_in[5];  // [2] f32
    float* out = (float*)d_out;

    k_dots <<<NTOK/16, 256>>>(h, W);
    k_scan <<<PB, 1024>>>(gum, mask, special, bias, out);
    k_merge<<<NTOK, 256>>>(h, out);
}

// round 13
// speedup vs baseline: 1.1640x; 1.1640x over previous
#include <cuda_runtime.h>
#include <cstdint>

// Problem constants
#define PB 8
#define PS 2048
#define PH 2048
#define NTOK (PB*PS)         // 16384

// Output layout: concatenated returns (all float32)
#define O_MH  0L
#define O_MAM (O_MH  + (long)PB*PS*PH)   // 33554432
#define O_MS  (O_MAM + (long)PB*PS)
#define O_CNT (O_MS  + (long)PB*PS)
#define O_MM  (O_CNT + (long)PB*PS)
#define O_LOG (O_MM  + (long)PB*PS*2)

// Scratch (device globals; no allocation allowed)
__device__ float4 g_dots[NTOK];      // per token: (h·Wa0, h·Wa1, h·Wb0, h·Wb1)
__device__ float  g_v[NTOK];
__device__ int    g_segstart[NTOK];
__device__ int    g_newlen[PB];
__device__ int    g_T[PB];

// ---------------------------------------------------------------------------
// Kernel A: per-token 4-way dot products.
// 128-thread blocks, 4 tokens/warp (16/block), grid = 1024.
// NO smem: W (32KB) is read via __ldg and stays L1-resident (every block
// reads the same lines). This keeps R3's 16-deep per-warp load batching
// while letting ~9 blocks/SM fill the chip (R3 was grid-limited at 512
// blocks; R4's 2-token warps halved MLP).
// ---------------------------------------------------------------------------
__global__ __launch_bounds__(128) void k_dots(const float* __restrict__ h,
                                              const float* __restrict__ W) {
    const int tid = threadIdx.x;
    const int warp = tid >> 5, lane = tid & 31;
    const long g0 = (long)blockIdx.x * 16 + warp * 4;  // 4 tokens per warp
    const float4* hp = ((const float4*)h) + g0 * (PH/4);
    const float4* W4 = (const float4*)W;               // [4096,2] -> 2048 float4

    float a[4][4];
    #pragma unroll
    for (int i = 0; i < 4; i++)
        #pragma unroll
        for (int c = 0; c < 4; c++) a[i][c] = 0.f;

    #pragma unroll 4
    for (int j = 0; j < 16; j++) {
        const int f = lane + 32 * j;           // float4 index within h row
        // 4 independent h loads per lane (DRAM stream)
        float4 x[4];
        #pragma unroll
        for (int i = 0; i < 4; i++) x[i] = hp[(long)i * (PH/4) + f];
        // W rows 4f..4f+3: Wa pairs in W4[2f], W4[2f+1]; Wb at +1024 (L1 hits)
        const float4 wa0 = __ldg(W4 + 2*f);
        const float4 wa1 = __ldg(W4 + 2*f + 1);
        const float4 wb0 = __ldg(W4 + 1024 + 2*f);
        const float4 wb1 = __ldg(W4 + 1024 + 2*f + 1);
        #pragma unroll
        for (int i = 0; i < 4; i++) {
            const float4 x4 = x[i];
            a[i][0] += x4.x*wa0.x + x4.y*wa0.z + x4.z*wa1.x + x4.w*wa1.z;
            a[i][1] += x4.x*wa0.y + x4.y*wa0.w + x4.z*wa1.y + x4.w*wa1.w;
            a[i][2] += x4.x*wb0.x + x4.y*wb0.z + x4.z*wb1.x + x4.w*wb1.z;
            a[i][3] += x4.x*wb0.y + x4.y*wb0.w + x4.z*wb1.y + x4.w*wb1.w;
        }
    }
    #pragma unroll
    for (int i = 0; i < 4; i++) {
        float v0 = a[i][0], v1 = a[i][1], v2 = a[i][2], v3 = a[i][3];
        #pragma unroll
        for (int o = 16; o > 0; o >>= 1) {
            v0 += __shfl_down_sync(0xFFFFFFFFu, v0, o);
            v1 += __shfl_down_sync(0xFFFFFFFFu, v1, o);
            v2 += __shfl_down_sync(0xFFFFFFFFu, v2, o);
            v3 += __shfl_down_sync(0xFFFFFFFFu, v3, o);
        }
        if (lane == 0) g_dots[g0 + i] = make_float4(v0, v1, v2, v3);
    }
}

// ---------------------------------------------------------------------------
// Kernel B: logits, gumbel argmax -> mm, per-batch run-length scan.
// One block per batch, 1024 threads, 2 positions per thread.
// ---------------------------------------------------------------------------
__global__ __launch_bounds__(1024) void k_scan(const float* __restrict__ gum,
                                               const int*   __restrict__ mask,
                                               const int*   __restrict__ special,
                                               const float* __restrict__ bias,
                                               float* __restrict__ out) {
    const int b = blockIdx.x, tid = threadIdx.x;
    __shared__ unsigned char sh_want[PS];
    __shared__ int sh_r[PS];
    __shared__ int sh_seg[PS];
    __shared__ int sh_scan[1024];
    __shared__ int warpsum[32];
    __shared__ int sh_T;

    const long base = (long)b * PS;

    const int m0 = mask[base + 2*tid], m1 = mask[base + 2*tid + 1];
    int partial = m0 + m1;
    #pragma unroll
    for (int o = 16; o > 0; o >>= 1) partial += __shfl_down_sync(0xFFFFFFFFu, partial, o);
    if ((tid & 31) == 0) warpsum[tid >> 5] = partial;
    __syncthreads();
    if (tid == 0) {
        int t = 0;
        #pragma unroll
        for (int i = 0; i < 32; i++) t += warpsum[i];
        sh_T = t;
    }
    __syncthreads();
    const int T = sh_T;
    const float b0 = bias[0], b1 = bias[1];

    float mmv[2][2], lg[2][2];
    #pragma unroll
    for (int p = 0; p < 2; p++) {
        const int s = 2*tid + p;
        const long gi = base + s;
        float l0, l1;
        if (s < PS - 1) {
            const float4 d0 = g_dots[gi];
            const float4 d1 = g_dots[gi + 1];
            l0 = d0.x + d1.z + b0;
            l1 = d0.y + d1.w + b1;
        } else { l0 = b0; l1 = b1; }
        lg[p][0] = l0; lg[p][1] = l1;
        const float gg0 = gum[gi*2], gg1 = gum[gi*2 + 1];
        const int idx1 = (l1 + gg1) > (l0 + gg0);  // argmax: first index wins ties
        float mm0 = idx1 ? 0.f : 1.f;
        float mm1 = idx1 ? 1.f : 0.f;
        if (special[gi]) { mm0 = 1.f; mm1 = 0.f; }
        const float mk = (float)((p == 0) ? m0 : m1);
        mm0 *= mk; mm1 *= mk;
        mmv[p][0] = mm0; mmv[p][1] = mm1;
        sh_want[s] = (mm1 > 0.5f) && (s >= 1) && (s < T - 1);
    }
    __syncthreads();

    int inc0, inc1;
    {
        const int s0 = 2*tid;
        inc0 = (s0 >= 1 && s0 < T) && !(sh_want[s0] && sh_want[s0-1]);
        const int s1 = 2*tid + 1;
        inc1 = (s1 < T) && !(sh_want[s1] && sh_want[s1-1]);
    }
    const int local = inc0 + inc1;
    sh_scan[tid] = local;
    __syncthreads();
    for (int off = 1; off < 1024; off <<= 1) {
        const int val = sh_scan[tid];
        const int add = (tid >= off) ? sh_scan[tid - off] : 0;
        __syncthreads();
        sh_scan[tid] = val + add;
        __syncthreads();
    }
    const int excl = sh_scan[tid] - local;
    const int r0 = excl + inc0;
    const int r1 = r0 + inc1;
    sh_r[2*tid]     = r0;
    sh_r[2*tid + 1] = r1;
    __syncthreads();
    const int new_len = sh_r[PS - 1] + 1;

    #pragma unroll
    for (int p = 0; p < 2; p++) {
        const int s = 2*tid + p;
        const int rr = sh_r[s];
        if (s == 0 || sh_r[s-1] != rr) sh_seg[rr] = s;
    }
    __syncthreads();

    #pragma unroll
    for (int p = 0; p < 2; p++) {
        const int s = 2*tid + p;
        const long gi = base + s;
        const bool want = sh_want[s];
        float v = want ? mmv[p][1] : mmv[p][0];
        if (s == 0) v = 1.f;
        if (s >= T) v = 0.f;
        g_v[gi] = v;

        ((float2*)(out + O_MM ))[gi] = make_float2(mmv[p][0], mmv[p][1]);
        ((float2*)(out + O_LOG))[gi] = make_float2(lg[p][0], lg[p][1]);

        const int t = s;  // output-row index
        float cnt = 0.f, mam = 0.f, msp = 0.f;
        if (t < new_len) {
            const int e = (t + 1 < new_len) ? sh_seg[t + 1] : T;
            cnt = (float)(e - sh_seg[t]);
            mam = 1.f;
            msp = (t == 0 || t == new_len - 1) ? 1.f : 0.f;
            g_segstart[gi] = sh_seg[t];
        }
        out[O_CNT + gi] = cnt;
        out[O_MAM + gi] = mam;
        out[O_MS  + gi] = msp;
    }
    if (tid == 0) { g_newlen[b] = new_len; g_T[b] = T; }
}

// ---------------------------------------------------------------------------
// Kernel C: merged_hidden via segment sums. One block per output row.
// Reversed block->token order to consume k_dots' L2-resident tail of h first.
// h reads are single-use here (transform rows partition inputs) -> __ldcs.
// Output stores __stcs so 134MB of writes don't evict other blocks' h lines.
// Branch-free inner loop so loads batch (MLP). (These k_merge choices
// measured ~8us better than R3's variant -- keep.)
// ---------------------------------------------------------------------------
__global__ __launch_bounds__(256) void k_merge(const float* __restrict__ h,
                                               float* __restrict__ out) {
    const int idx = NTOK - 1 - blockIdx.x;   // reversed
    const int t = idx & (PS - 1);
    const int b = idx >> 11;
    const int tid = threadIdx.x;
    const int nl = g_newlen[b];
    float4* op = ((float4*)(out + O_MH)) + ((long)idx) * (PH/4);

    if (t >= nl) {
        const float4 z = make_float4(0.f, 0.f, 0.f, 0.f);
        __stcs(op + tid, z);
        __stcs(op + tid + 256, z);
        return;
    }
    const long base = (long)b * PS;
    const int s0 = g_segstart[base + t];
    const int s1 = (t + 1 < nl) ? g_segstart[base + t + 1] : g_T[b];
    float4 a0 = make_float4(0.f,0.f,0.f,0.f);
    float4 a1 = make_float4(0.f,0.f,0.f,0.f);
    #pragma unroll 2
    for (int s = s1 - 1; s >= s0; s--) {        // high addresses first (hotter in L2)
        const float vv = g_v[base + s];
        const float4* hp = ((const float4*)h) + (base + s) * (long)(PH/4);
        const float4 x0 = __ldcs(hp + tid);
        const float4 x1 = __ldcs(hp + tid + 256);
        a0.x += vv*x0.x; a0.y += vv*x0.y; a0.z += vv*x0.z; a0.w += vv*x0.w;
        a1.x += vv*x1.x; a1.y += vv*x1.y; a1.z += vv*x1.z; a1.w += vv*x1.w;
    }
    __stcs(op + tid, a0);
    __stcs(op + tid + 256, a1);
}

// ---------------------------------------------------------------------------
extern "C" void kernel_launch(void* const* d_in, const int* in_sizes, int n_in,
                              void* d_out, int out_size) {
    const float* h       = (const float*)d_in[0];  // [8,2048,2048] f32
    const int*   mask    = (const int*)  d_in[1];  // [8,2048] i32
    const int*   special = (const int*)  d_in[2];  // [8,2048] i32
    const float* gum     = (const float*)d_in[3];  // [8,2048,2] f32
    const float* W       = (const float*)d_in[4];  // [4096,2] f32
    const float* bias    = (const float*)d_in[5];  // [2] f32
    float* out = (float*)d_out;

    k_dots <<<NTOK/16, 128>>>(h, W);
    k_scan <<<PB, 1024>>>(gum, mask, special, bias, out);
    k_merge<<<NTOK, 256>>>(h, out);
}